// round 12
// baseline (speedup 1.0000x reference)
#include <cuda_runtime.h>
#include <cuda_fp16.h>

#define NB     16384
#define NNODES 55
#define NTOT   (NB * NNODES)      // 901120
#define ECNT   (4 * NTOT)         // 3604480
#define SCAN_CH 4096
#define SCAN_NB (NTOT / SCAN_CH)  // 220 exactly

#define PROJ_BLOCKS 7040          // 7040 * 8 warps * 16 nodes = 901120
#define AGG_BLOCKS 14080          // 14080 * 4 warps * 16 nodes = 901120

// ---------------- device scratch ----------------
__device__ __half g_paA[NTOT * 32];
__device__ __half g_paB[NTOT * 32];
__device__ __half g_psA[NTOT * 32];
__device__ __half g_psB[NTOT * 32];
__device__ __half g_jk[NTOT * 32];
__device__ int    g_deg[NTOT];
__device__ int    g_rowptr[NTOT];
__device__ int    g_cursor[NTOT];
__device__ int    g_col[ECNT];
__device__ int    g_bsum[256];
__device__ float  g_A[1024], g_W2[1024], g_u[32], g_v[32], g_b2[32], g_c[1];

__device__ __forceinline__ float selu_f(float x) {
    const float sc = 1.0507009873554805f;
    const float sa = 1.7580993408473766f;  // sc * alpha
    return x > 0.f ? sc * x : sa * expm1f(x);
}

__device__ __forceinline__ void mma16816(float& d0, float& d1, float& d2, float& d3,
                                         unsigned a0, unsigned a1, unsigned a2, unsigned a3,
                                         unsigned b0, unsigned b1) {
    asm volatile("mma.sync.aligned.m16n8k16.row.col.f32.f16.f16.f32 "
                 "{%0,%1,%2,%3}, {%4,%5,%6,%7}, {%8,%9}, {%0,%1,%2,%3};"
                 : "+f"(d0), "+f"(d1), "+f"(d2), "+f"(d3)
                 : "r"(a0), "r"(a1), "r"(a2), "r"(a3), "r"(b0), "r"(b1));
}

// ---------------- attention precompute ----------------
__global__ void __launch_bounds__(256) k_prep(
        const float* __restrict__ wq, const float* __restrict__ bq,
        const float* __restrict__ wk, const float* __restrict__ bk,
        const float* __restrict__ wv, const float* __restrict__ bv,
        const float* __restrict__ wo, const float* __restrict__ bo) {
    int tid = threadIdx.x;
    for (int i = tid; i < 1024; i += 256) {
        int d = i >> 5, e = i & 31;
        float a = 0.f, w2 = 0.f;
        for (int o = 0; o < 32; o++) {
            a  += wq[d * 32 + o] * wk[e * 32 + o];
            w2 += wv[d * 32 + o] * wo[o * 32 + e];
        }
        g_A[d * 32 + e]  = a;
        g_W2[d * 32 + e] = w2;
    }
    if (tid < 32) {
        float u = 0.f, v = 0.f, b2 = 0.f;
        for (int o = 0; o < 32; o++) {
            u  += wq[tid * 32 + o] * bk[o];
            v  += wk[tid * 32 + o] * bq[o];
            b2 += bv[o] * wo[o * 32 + tid];
        }
        g_u[tid] = u; g_v[tid] = v; g_b2[tid] = b2 + bo[tid];
    }
    if (tid == 0) {
        float c = 0.f;
        for (int o = 0; o < 32; o++) c += bq[o] * bk[o];
        g_c[0] = c;
    }
}

// ---------------- CSR build ----------------
__global__ void __launch_bounds__(256) k_zero() {
    int i = blockIdx.x * blockDim.x + threadIdx.x;
    if (i < NTOT) g_deg[i] = 0;
}
__global__ void __launch_bounds__(256) k_hist(const int* __restrict__ ei) {
    int e = blockIdx.x * blockDim.x + threadIdx.x;
    if (e < ECNT) atomicAdd(&g_deg[ei[ECNT + e]], 1);
}
__global__ void __launch_bounds__(1024) k_scan1() {
    __shared__ int wsum[32];
    int t = threadIdx.x;
    int base = blockIdx.x * SCAN_CH + t * 4;
    int v0 = g_deg[base], v1 = g_deg[base + 1], v2 = g_deg[base + 2], v3 = g_deg[base + 3];
    int s = v0 + v1 + v2 + v3;
    int lane = t & 31, wid = t >> 5;
    int incl = s;
#pragma unroll
    for (int off = 1; off < 32; off <<= 1) {
        int n = __shfl_up_sync(0xffffffffu, incl, off);
        if (lane >= off) incl += n;
    }
    if (lane == 31) wsum[wid] = incl;
    __syncthreads();
    if (wid == 0) {
        int wv = wsum[lane];
        int wincl = wv;
#pragma unroll
        for (int off = 1; off < 32; off <<= 1) {
            int n = __shfl_up_sync(0xffffffffu, wincl, off);
            if (lane >= off) wincl += n;
        }
        wsum[lane] = wincl - wv;
        if (lane == 31) g_bsum[blockIdx.x] = wincl;
    }
    __syncthreads();
    int excl = wsum[wid] + (incl - s);
    g_rowptr[base]     = excl;
    g_rowptr[base + 1] = excl + v0;
    g_rowptr[base + 2] = excl + v0 + v1;
    g_rowptr[base + 3] = excl + v0 + v1 + v2;
}
__global__ void __launch_bounds__(256) k_scan2() {
    __shared__ int s[256];
    int t = threadIdx.x;
    s[t] = (t < SCAN_NB) ? g_bsum[t] : 0;
    __syncthreads();
    if (t == 0) {
        int run = 0;
        for (int i = 0; i < SCAN_NB; i++) { int v = s[i]; s[i] = run; run += v; }
    }
    __syncthreads();
    if (t < SCAN_NB) g_bsum[t] = s[t];
}
__global__ void __launch_bounds__(256) k_scan3() {
    int i = blockIdx.x * blockDim.x + threadIdx.x;
    if (i < NTOT) {
        int r = g_rowptr[i] + g_bsum[i >> 12];
        g_rowptr[i] = r;
        g_cursor[i] = r;
    }
}
__global__ void __launch_bounds__(256) k_fill(const int* __restrict__ ei) {
    int e = blockIdx.x * blockDim.x + threadIdx.x;
    if (e < ECNT) {
        int s = ei[e];
        int d = ei[ECNT + e];
        int p = atomicAdd(&g_cursor[d], 1);
        g_col[p] = s;
    }
}

// ---------------- layer-0 projection: x[13] -> pa(half) = x@wl0, ps(half) = x@wr0 + bl0 ----------------
__global__ void __launch_bounds__(256) k_proj0(const float* __restrict__ x,
                                               const float* __restrict__ wl0,
                                               const float* __restrict__ wr0,
                                               const float* __restrict__ bl0,
                                               __half* __restrict__ paOut,
                                               __half* __restrict__ psOut) {
    __shared__ float2 wS[13 * 32];
    __shared__ float  blS[32];
    int tid = threadIdx.x, t = tid & 31, w = tid >> 5;
    for (int i = tid; i < 13 * 32; i += 256)
        wS[i] = make_float2(wl0[i], wr0[i]);
    if (tid < 32) blS[tid] = bl0[tid];
    __syncthreads();

    int wg = blockIdx.x * 8 + w;
    for (int it = 0; it < 16; it++) {
        int n = wg * 16 + it;
        float xv = (t < 13) ? x[(size_t)n * 13 + t] : 0.f;
        float apa = 0.f, aps = 0.f;
#pragma unroll
        for (int k = 0; k < 13; k++) {
            float xk = __shfl_sync(0xffffffffu, xv, k);
            float2 w2 = wS[k * 32 + t];
            apa = fmaf(xk, w2.x, apa);
            aps = fmaf(xk, w2.y, aps);
        }
        size_t idx = (size_t)n * 32 + t;
        paOut[idx] = __float2half_rn(apa);
        __stcs(&psOut[idx], __float2half_rn(aps + blS[t]));
    }
}

// ---------------- fused aggregate + selu + jk + mma projection ----------------
// Each warp owns 16 nodes (one M16 mma tile). o staged in smem as fp16,
// pa' | ps' computed with mma.m16n8k16 against combined B = [wl | wr] (fp16).
template <int MODE, int DO_PROJ>
__global__ void __launch_bounds__(128) k_aggproj(const __half* __restrict__ paIn,
                                                 const __half* __restrict__ psIn,
                                                 __half* __restrict__ paOut,
                                                 __half* __restrict__ psOut,
                                                 const float* __restrict__ wl,
                                                 const float* __restrict__ wr,
                                                 const float* __restrict__ bl) {
    __shared__ __half oT[4][16][32];
    __shared__ float  blS[32];
    int tid = threadIdx.x, t = tid & 31, w = tid >> 5;
    int g4 = t >> 2, tig = t & 3;

    unsigned bfr[8][2][2];
    if (DO_PROJ) {
#pragma unroll
        for (int j = 0; j < 8; j++) {
            int n = j * 8 + g4;
            const float* Wp = (n < 32) ? (wl + n) : (wr + (n - 32));
#pragma unroll
            for (int s = 0; s < 2; s++) {
                int k0 = s * 16 + tig * 2;
                __half2 b0 = __floats2half2_rn(Wp[k0 * 32],       Wp[(k0 + 1) * 32]);
                __half2 b1 = __floats2half2_rn(Wp[(k0 + 8) * 32], Wp[(k0 + 9) * 32]);
                bfr[j][s][0] = *(unsigned*)&b0;
                bfr[j][s][1] = *(unsigned*)&b1;
            }
        }
        if (tid < 32) blS[tid] = bl[tid];
        __syncthreads();
    }

    int wg = blockIdx.x * 4 + w;          // 56320 warps * 16 nodes = NTOT
    int nbase = wg * 16;

    // pipeline: preload node it+1's CSR info while processing node it
    int sN = g_rowptr[nbase];
    int dN = g_deg[nbase];
    int colrN = (t < min(dN, 32)) ? g_col[sN + t] : 0;

    for (int it = 0; it < 16; it++) {
        int n = nbase + it;
        int s = sN, d = dN, colr = colrN;
        if (it < 15) {
            int nn = n + 1;
            sN = g_rowptr[nn];
            dN = g_deg[nn];
            colrN = (t < min(dN, 32)) ? g_col[sN + t] : 0;
        }

        int dlim = min(d, 32);
        float acc = 0.f;
        int e = 0;
        for (; e + 4 <= dlim; e += 4) {
            int c0 = __shfl_sync(0xffffffffu, colr, e);
            int c1 = __shfl_sync(0xffffffffu, colr, e + 1);
            int c2 = __shfl_sync(0xffffffffu, colr, e + 2);
            int c3 = __shfl_sync(0xffffffffu, colr, e + 3);
            float v0 = __half2float(__ldg(&paIn[(size_t)c0 * 32 + t]));
            float v1 = __half2float(__ldg(&paIn[(size_t)c1 * 32 + t]));
            float v2 = __half2float(__ldg(&paIn[(size_t)c2 * 32 + t]));
            float v3 = __half2float(__ldg(&paIn[(size_t)c3 * 32 + t]));
            acc += (v0 + v1) + (v2 + v3);
        }
        for (; e < dlim; e++) {
            int c = __shfl_sync(0xffffffffu, colr, e);
            acc += __half2float(__ldg(&paIn[(size_t)c * 32 + t]));
        }
        for (int e2 = 32; e2 < d; e2++) {       // pathological-degree tail
            int c = g_col[s + e2];
            acc += __half2float(__ldg(&paIn[(size_t)c * 32 + t]));
        }

        size_t idx = (size_t)n * 32 + t;
        float o = acc * (1.f / (float)max(d, 1)) + __half2float(__ldcs(&psIn[idx]));
        o = selu_f(o);

        if (MODE == 0) {
            __stcs(&g_jk[idx], __float2half_rn(o));
        } else {
            float old = __half2float(__ldcs(&g_jk[idx]));
            __stcs(&g_jk[idx], __float2half_rn(fmaxf(old, o)));
        }

        if (DO_PROJ) oT[w][it][t] = __float2half_rn(o);
    }

    if (DO_PROJ) {
        __syncwarp();
        // A fragments: A[node 0..15][k 0..31] from oT[w]
        const __half* ow = &oT[w][0][0];   // [16][32]
        unsigned a[2][4];
#pragma unroll
        for (int s = 0; s < 2; s++) {
            int kc = tig * 2 + s * 16;
            a[s][0] = *(const unsigned*)(ow + (g4)     * 32 + kc);
            a[s][1] = *(const unsigned*)(ow + (g4 + 8) * 32 + kc);
            a[s][2] = *(const unsigned*)(ow + (g4)     * 32 + kc + 8);
            a[s][3] = *(const unsigned*)(ow + (g4 + 8) * 32 + kc + 8);
        }
#pragma unroll
        for (int j = 0; j < 8; j++) {
            float d0 = 0.f, d1 = 0.f, d2 = 0.f, d3 = 0.f;
            mma16816(d0, d1, d2, d3, a[0][0], a[0][1], a[0][2], a[0][3],
                     bfr[j][0][0], bfr[j][0][1]);
            mma16816(d0, d1, d2, d3, a[1][0], a[1][1], a[1][2], a[1][3],
                     bfr[j][1][0], bfr[j][1][1]);
            int n0 = j * 8 + tig * 2;         // global output col of d0 (d1 = n0+1)
            size_t rowLo = (size_t)(nbase + g4)     * 32;
            size_t rowHi = (size_t)(nbase + g4 + 8) * 32;
            if (j < 4) {
                __half2 lo = __floats2half2_rn(d0, d1);
                __half2 hi = __floats2half2_rn(d2, d3);
                *(__half2*)(paOut + rowLo + n0) = lo;
                *(__half2*)(paOut + rowHi + n0) = hi;
            } else {
                float b0 = blS[n0 - 32], b1 = blS[n0 - 31];
                __half2 lo = __floats2half2_rn(d0 + b0, d1 + b1);
                __half2 hi = __floats2half2_rn(d2 + b0, d3 + b1);
                __stcs((__half2*)(psOut + rowLo + n0 - 32), lo);
                __stcs((__half2*)(psOut + rowHi + n0 - 32), hi);
            }
        }
    }
}

// ---------------- attention (1 warp per graph, 4 graphs per 128-thread block) ----------------
__device__ __forceinline__ int sel6(const int o0, const int o1, const int o2,
                                    const int o3, const int o4, const int o5, int si) {
    int r = o0;
    r = (si == 1) ? o1 : r;
    r = (si == 2) ? o2 : r;
    r = (si == 3) ? o3 : r;
    r = (si == 4) ? o4 : r;
    r = (si == 5) ? o5 : r;
    return r;
}

__global__ void __launch_bounds__(128) k_attn(const float* __restrict__ x,
                                              const int* __restrict__ shuf,
                                              const float* __restrict__ wfc,
                                              const float* __restrict__ bfc,
                                              float* __restrict__ out) {
    __shared__ float sA[1024], sW2[1024], sU[32], sV[32], sB2[32];
    __shared__ float sKeys[4][55 * 33];
    __shared__ float sQa[4][6 * 33];
    __shared__ float sKb[4][56];
    __shared__ float sAt[4][6 * 56];

    int tid = threadIdx.x, t = tid & 31, w = tid >> 5;

    for (int i = tid; i < 1024; i += 128) { sA[i] = g_A[i]; sW2[i] = g_W2[i]; }
    if (tid < 32) { sU[tid] = g_u[tid]; sV[tid] = g_v[tid]; sB2[tid] = g_b2[tid]; }
    __syncthreads();

    float cterm = g_c[0];
    int g = blockIdx.x * 4 + w;
    int nbase = g * NNODES;

    unsigned b0 = __ballot_sync(0xffffffffu, x[(size_t)(nbase + t) * 13 + 10] > 0.5f);
    unsigned b1 = __ballot_sync(0xffffffffu,
                                (t < 23) ? (x[(size_t)(nbase + 32 + t) * 13 + 10] > 0.5f) : false);
    int ord[6];
#pragma unroll
    for (int j = 0; j < 6; j++) {
        if (b0) { int p = __ffs(b0) - 1; b0 &= b0 - 1; ord[j] = p; }
        else    { int p = __ffs(b1) - 1; b1 &= b1 - 1; ord[j] = 32 + p; }
    }
    int qr[6];
#pragma unroll
    for (int j = 0; j < 6; j++) {
        int si = shuf[(size_t)g * 6 + j];
        qr[j] = sel6(ord[0], ord[1], ord[2], ord[3], ord[4], ord[5], si);
    }

    for (int k = 0; k < 55; k++)
        sKeys[w][k * 33 + t] = selu_f(__half2float(__ldg(&g_jk[(size_t)(nbase + k) * 32 + t])));
    __syncwarp();

    {
        float acc = cterm;
#pragma unroll
        for (int d = 0; d < 32; d++) acc += sKeys[w][t * 33 + d] * sV[d];
        sKb[w][t] = acc;
        if (t < 23) {
            float a2 = cterm;
#pragma unroll
            for (int d = 0; d < 32; d++) a2 += sKeys[w][(t + 32) * 33 + d] * sV[d];
            sKb[w][t + 32] = a2;
        }
    }

    float qu[6];
#pragma unroll
    for (int q = 0; q < 6; q++) {
        const float* kr = &sKeys[w][qr[q] * 33];
        float pp = kr[t] * sU[t];
#pragma unroll
        for (int off = 16; off; off >>= 1) pp += __shfl_xor_sync(0xffffffffu, pp, off);
        qu[q] = pp;
        float a = 0.f;
#pragma unroll
        for (int d = 0; d < 32; d++) a += kr[d] * sA[d * 32 + t];
        sQa[w][q * 33 + t] = a;
    }
    __syncwarp();

    const float isq = 0.17677669529663687f;  // 1/sqrt(32)
#pragma unroll
    for (int q = 0; q < 6; q++) {
        const float* qa = &sQa[w][q * 33];
        int k1 = (t < 23) ? (t + 32) : 54;
        float s0 = qu[q] + sKb[w][t];
        float s1 = qu[q] + sKb[w][k1];
#pragma unroll
        for (int d = 0; d < 32; d++) {
            float qv = qa[d];
            s0 += qv * sKeys[w][t * 33 + d];
            s1 += qv * sKeys[w][k1 * 33 + d];
        }
        s0 *= isq; s1 *= isq;
        if (t >= 23) s1 = -1e30f;
        float m = fmaxf(s0, s1);
#pragma unroll
        for (int off = 16; off; off >>= 1) m = fmaxf(m, __shfl_xor_sync(0xffffffffu, m, off));
        float e0 = __expf(s0 - m);
        float e1 = (t < 23) ? __expf(s1 - m) : 0.f;
        float sum = e0 + e1;
#pragma unroll
        for (int off = 16; off; off >>= 1) sum += __shfl_xor_sync(0xffffffffu, sum, off);
        float inv = 1.f / sum;
        sAt[w][q * 56 + t] = e0 * inv;
        if (t < 23) sAt[w][q * 56 + t + 32] = e1 * inv;
    }
    __syncwarp();

#pragma unroll
    for (int q = 0; q < 6; q++) {
        float c2 = 0.f;
        for (int k = 0; k < 55; k++) c2 += sAt[w][q * 56 + k] * sKeys[w][k * 33 + t];
        sQa[w][q * 33 + t] = c2;
    }
    __syncwarp();

#pragma unroll
    for (int q = 0; q < 6; q++) {
        float o = sB2[t];
#pragma unroll
        for (int d = 0; d < 32; d++) o += sQa[w][q * 33 + d] * sW2[d * 32 + t];
        sKeys[w][q * 32 + t] = selu_f(o);
    }
    __syncwarp();

    float pj[6] = {0.f, 0.f, 0.f, 0.f, 0.f, 0.f};
#pragma unroll
    for (int i = 0; i < 6; i++) {
        int e = i * 32 + t;
        float v = sKeys[w][e];
#pragma unroll
        for (int j = 0; j < 6; j++) pj[j] += v * wfc[e * 6 + j];
    }
#pragma unroll
    for (int j = 0; j < 6; j++) {
#pragma unroll
        for (int off = 16; off; off >>= 1) pj[j] += __shfl_xor_sync(0xffffffffu, pj[j], off);
    }
    if (t == 0) {
#pragma unroll
        for (int j = 0; j < 6; j++) out[(size_t)g * 6 + j] = pj[j] + bfc[j];
    }
}

// ---------------- launch ----------------
extern "C" void kernel_launch(void* const* d_in, const int* in_sizes, int n_in,
                              void* d_out, int out_size) {
    const float* x    = (const float*)d_in[0];
    const int*   ei   = (const int*)d_in[1];     // int32 (JAX demotes int64)
    const int*   shuf = (const int*)d_in[2];     // int32
    const float* wl0 = (const float*)d_in[3];
    const float* bl0 = (const float*)d_in[4];
    const float* wr0 = (const float*)d_in[5];
    const float* wl  = (const float*)d_in[6];
    const float* bl  = (const float*)d_in[7];
    const float* wr  = (const float*)d_in[8];
    const float* wq  = (const float*)d_in[9];
    const float* bq  = (const float*)d_in[10];
    const float* wk  = (const float*)d_in[11];
    const float* bk  = (const float*)d_in[12];
    const float* wv  = (const float*)d_in[13];
    const float* bv  = (const float*)d_in[14];
    const float* wo  = (const float*)d_in[15];
    const float* bo  = (const float*)d_in[16];
    const float* wfc = (const float*)d_in[17];
    const float* bfc = (const float*)d_in[18];
    float* out = (float*)d_out;

    __half *paA, *paB, *psA, *psB;
    cudaGetSymbolAddress((void**)&paA, g_paA);
    cudaGetSymbolAddress((void**)&paB, g_paB);
    cudaGetSymbolAddress((void**)&psA, g_psA);
    cudaGetSymbolAddress((void**)&psB, g_psB);

    k_prep<<<1, 256>>>(wq, bq, wk, bk, wv, bv, wo, bo);
    k_zero<<<(NTOT + 255) / 256, 256>>>();
    k_hist<<<(ECNT + 255) / 256, 256>>>(ei);
    k_scan1<<<SCAN_NB, 1024>>>();
    k_scan2<<<1, 256>>>();
    k_scan3<<<(NTOT + 255) / 256, 256>>>();
    k_fill<<<(ECNT + 255) / 256, 256>>>(ei);

    // layer-1 inputs
    k_proj0<<<PROJ_BLOCKS, 256>>>(x, wl0, wr0, bl0, paA, psA);
    // layer 1 (jk = h1) + project layer-2 inputs
    k_aggproj<0, 1><<<AGG_BLOCKS, 128>>>(paA, psA, paB, psB,
                                         wl + 0 * 1024, wr + 0 * 1024, bl + 0 * 32);
    // layers 2..4 (jk = max) + project next
    k_aggproj<1, 1><<<AGG_BLOCKS, 128>>>(paB, psB, paA, psA,
                                         wl + 1 * 1024, wr + 1 * 1024, bl + 1 * 32);
    k_aggproj<1, 1><<<AGG_BLOCKS, 128>>>(paA, psA, paB, psB,
                                         wl + 2 * 1024, wr + 2 * 1024, bl + 2 * 32);
    k_aggproj<1, 1><<<AGG_BLOCKS, 128>>>(paB, psB, paA, psA,
                                         wl + 3 * 1024, wr + 3 * 1024, bl + 3 * 32);
    // layer 5: aggregate + jk only
    k_aggproj<1, 0><<<AGG_BLOCKS, 128>>>(paA, psA, nullptr, nullptr,
                                         nullptr, nullptr, nullptr);

    k_attn<<<NB / 4, 128>>>(x, shuf, wfc, bfc, out);
}

// round 13
// speedup vs baseline: 1.0276x; 1.0276x over previous
#include <cuda_runtime.h>
#include <cuda_fp16.h>

#define NB     16384
#define NNODES 55
#define NTOT   (NB * NNODES)      // 901120
#define ECNT   (4 * NTOT)         // 3604480
#define SCAN_CH 4096
#define SCAN_NB (NTOT / SCAN_CH)  // 220 exactly

#define PROJ_BLOCKS 7040          // 7040 * 8 warps * 16 nodes = 901120
#define AGG_BLOCKS  7040          // 7040 * 8 warps * 16 nodes = 901120

#define FULLM 0xffffffffu

// ---------------- device scratch ----------------
__device__ __half g_paA[NTOT * 32];
__device__ __half g_paB[NTOT * 32];
__device__ __half g_psA[NTOT * 32];
__device__ __half g_psB[NTOT * 32];
__device__ __half g_jk[NTOT * 32];
__device__ int    g_deg[NTOT];
__device__ int    g_rowptr[NTOT];
__device__ int    g_cursor[NTOT];
__device__ int    g_col[ECNT];
__device__ int    g_bsum[256];
__device__ float  g_A[1024], g_W2[1024], g_u[32], g_v[32], g_b2[32], g_c[1];

__device__ __forceinline__ float selu_f(float x) {
    const float sc = 1.0507009873554805f;
    const float sa = 1.7580993408473766f;  // sc * alpha
    return x > 0.f ? sc * x : sa * expm1f(x);
}

__device__ __forceinline__ void mma16816(float& d0, float& d1, float& d2, float& d3,
                                         unsigned a0, unsigned a1, unsigned a2, unsigned a3,
                                         unsigned b0, unsigned b1) {
    asm volatile("mma.sync.aligned.m16n8k16.row.col.f32.f16.f16.f32 "
                 "{%0,%1,%2,%3}, {%4,%5,%6,%7}, {%8,%9}, {%0,%1,%2,%3};"
                 : "+f"(d0), "+f"(d1), "+f"(d2), "+f"(d3)
                 : "r"(a0), "r"(a1), "r"(a2), "r"(a3), "r"(b0), "r"(b1));
}

// ---------------- attention precompute ----------------
__global__ void __launch_bounds__(256) k_prep(
        const float* __restrict__ wq, const float* __restrict__ bq,
        const float* __restrict__ wk, const float* __restrict__ bk,
        const float* __restrict__ wv, const float* __restrict__ bv,
        const float* __restrict__ wo, const float* __restrict__ bo) {
    int tid = threadIdx.x;
    for (int i = tid; i < 1024; i += 256) {
        int d = i >> 5, e = i & 31;
        float a = 0.f, w2 = 0.f;
        for (int o = 0; o < 32; o++) {
            a  += wq[d * 32 + o] * wk[e * 32 + o];
            w2 += wv[d * 32 + o] * wo[o * 32 + e];
        }
        g_A[d * 32 + e]  = a;
        g_W2[d * 32 + e] = w2;
    }
    if (tid < 32) {
        float u = 0.f, v = 0.f, b2 = 0.f;
        for (int o = 0; o < 32; o++) {
            u  += wq[tid * 32 + o] * bk[o];
            v  += wk[tid * 32 + o] * bq[o];
            b2 += bv[o] * wo[o * 32 + tid];
        }
        g_u[tid] = u; g_v[tid] = v; g_b2[tid] = b2 + bo[tid];
    }
    if (tid == 0) {
        float c = 0.f;
        for (int o = 0; o < 32; o++) c += bq[o] * bk[o];
        g_c[0] = c;
    }
}

// ---------------- CSR build ----------------
__global__ void __launch_bounds__(256) k_zero() {
    int i = blockIdx.x * blockDim.x + threadIdx.x;
    if (i < NTOT) g_deg[i] = 0;
}
__global__ void __launch_bounds__(256) k_hist(const int* __restrict__ ei) {
    int e = blockIdx.x * blockDim.x + threadIdx.x;
    if (e < ECNT) atomicAdd(&g_deg[ei[ECNT + e]], 1);
}
__global__ void __launch_bounds__(1024) k_scan1() {
    __shared__ int wsum[32];
    int t = threadIdx.x;
    int base = blockIdx.x * SCAN_CH + t * 4;
    int v0 = g_deg[base], v1 = g_deg[base + 1], v2 = g_deg[base + 2], v3 = g_deg[base + 3];
    int s = v0 + v1 + v2 + v3;
    int lane = t & 31, wid = t >> 5;
    int incl = s;
#pragma unroll
    for (int off = 1; off < 32; off <<= 1) {
        int n = __shfl_up_sync(FULLM, incl, off);
        if (lane >= off) incl += n;
    }
    if (lane == 31) wsum[wid] = incl;
    __syncthreads();
    if (wid == 0) {
        int wv = wsum[lane];
        int wincl = wv;
#pragma unroll
        for (int off = 1; off < 32; off <<= 1) {
            int n = __shfl_up_sync(FULLM, wincl, off);
            if (lane >= off) wincl += n;
        }
        wsum[lane] = wincl - wv;
        if (lane == 31) g_bsum[blockIdx.x] = wincl;
    }
    __syncthreads();
    int excl = wsum[wid] + (incl - s);
    g_rowptr[base]     = excl;
    g_rowptr[base + 1] = excl + v0;
    g_rowptr[base + 2] = excl + v0 + v1;
    g_rowptr[base + 3] = excl + v0 + v1 + v2;
}
__global__ void __launch_bounds__(256) k_scan2() {
    __shared__ int s[256];
    int t = threadIdx.x;
    s[t] = (t < SCAN_NB) ? g_bsum[t] : 0;
    __syncthreads();
    if (t == 0) {
        int run = 0;
        for (int i = 0; i < SCAN_NB; i++) { int v = s[i]; s[i] = run; run += v; }
    }
    __syncthreads();
    if (t < SCAN_NB) g_bsum[t] = s[t];
}
__global__ void __launch_bounds__(256) k_scan3() {
    int i = blockIdx.x * blockDim.x + threadIdx.x;
    if (i < NTOT) {
        int r = g_rowptr[i] + g_bsum[i >> 12];
        g_rowptr[i] = r;
        g_cursor[i] = r;
    }
}
__global__ void __launch_bounds__(256) k_fill(const int* __restrict__ ei) {
    int e = blockIdx.x * blockDim.x + threadIdx.x;
    if (e < ECNT) {
        int s = ei[e];
        int d = ei[ECNT + e];
        int p = atomicAdd(&g_cursor[d], 1);
        g_col[p] = s;
    }
}

// ---------------- layer-0 projection: x[13] -> pa(half) = x@wl0, ps(half) = x@wr0 + bl0 ----------------
__global__ void __launch_bounds__(256) k_proj0(const float* __restrict__ x,
                                               const float* __restrict__ wl0,
                                               const float* __restrict__ wr0,
                                               const float* __restrict__ bl0,
                                               __half* __restrict__ paOut,
                                               __half* __restrict__ psOut) {
    __shared__ float2 wS[13 * 32];
    __shared__ float  blS[32];
    int tid = threadIdx.x, t = tid & 31, w = tid >> 5;
    for (int i = tid; i < 13 * 32; i += 256)
        wS[i] = make_float2(wl0[i], wr0[i]);
    if (tid < 32) blS[tid] = bl0[tid];
    __syncthreads();

    int wg = blockIdx.x * 8 + w;
    for (int it = 0; it < 16; it++) {
        int n = wg * 16 + it;
        float xv = (t < 13) ? x[(size_t)n * 13 + t] : 0.f;
        float apa = 0.f, aps = 0.f;
#pragma unroll
        for (int k = 0; k < 13; k++) {
            float xk = __shfl_sync(FULLM, xv, k);
            float2 w2 = wS[k * 32 + t];
            apa = fmaf(xk, w2.x, apa);
            aps = fmaf(xk, w2.y, aps);
        }
        size_t idx = (size_t)n * 32 + t;
        paOut[idx] = __float2half_rn(apa);
        __stcs(&psOut[idx], __float2half_rn(aps + blS[t]));
    }
}

// ---------------- fused aggregate + selu + jk + mma projection ----------------
// 3-stage pipelined gather: iter i issues meta(i+3), colr(i+2), gather(i+1),
// consumes node i. Fixed 8-slot gather (deg>8 tail via memory fallback, ~2%).
// Projection: mma.m16n8k16 with B-fragments staged in shared memory.
template <int MODE, int DO_PROJ>
__global__ void __launch_bounds__(256) k_aggproj(const __half* __restrict__ paIn,
                                                 const __half* __restrict__ psIn,
                                                 __half* __restrict__ paOut,
                                                 __half* __restrict__ psOut,
                                                 const float* __restrict__ wl,
                                                 const float* __restrict__ wr,
                                                 const float* __restrict__ bl) {
    __shared__ __half   oT[8][16][32];
    __shared__ unsigned bF[1024];          // [j][s][r][lane] fragments of B=[wl|wr]
    __shared__ float    blS[32];
    int tid = threadIdx.x, t = tid & 31, w = tid >> 5;
    int g4 = t >> 2, tig = t & 3;

    if (DO_PROJ) {
        for (int i = tid; i < 1024; i += 256) {
            int lane = i & 31;
            int r = (i >> 5) & 1;
            int s = (i >> 6) & 1;
            int j = i >> 7;
            int n = j * 8 + (lane >> 2);
            const float* Wp = (n < 32) ? (wl + n) : (wr + (n - 32));
            int k0 = s * 16 + (lane & 3) * 2 + (r ? 8 : 0);
            __half2 b = __floats2half2_rn(Wp[k0 * 32], Wp[(k0 + 1) * 32]);
            bF[i] = *(unsigned*)&b;
        }
        if (tid < 32) blS[tid] = bl[tid];
        __syncthreads();
    }

    int wg = blockIdx.x * 8 + w;
    int nb = wg * 16;

    // ---- pipeline state ----
    int    colQ[2];                   // colr bank, parity of node
    int    sQ[2], dQ[2];              // meta aligned with colQ
    int    sC[2], dC[2];              // consume meta, parity of node
    __half hvQ[2][8];
    __half psQ[2], jkQ[2];
    int sM, dM;                       // meta for node (i+2) at iter i

    // ---- prologue ----
    {
        int s0 = g_rowptr[nb],     d0 = g_deg[nb];
        int s1 = g_rowptr[nb + 1], d1 = g_deg[nb + 1];
        sM = g_rowptr[nb + 2];  dM = g_deg[nb + 2];
        int colr0 = (t < min(d0, 32)) ? g_col[s0 + t] : 0;
        colQ[1] = (t < min(d1, 32)) ? g_col[s1 + t] : 0;
        sQ[1] = s1; dQ[1] = d1;
#pragma unroll
        for (int j = 0; j < 8; j++) {
            int c = (j < d0) ? __shfl_sync(FULLM, colr0, j) : nb;
            hvQ[0][j] = __ldg(&paIn[(size_t)c * 32 + t]);
        }
        psQ[0] = __ldcs(&psIn[(size_t)nb * 32 + t]);
        if (MODE) jkQ[0] = __ldcs(&g_jk[(size_t)nb * 32 + t]);
        sC[0] = s0; dC[0] = d0;
    }

#pragma unroll
    for (int i = 0; i < 16; i++) {
        int n = nb + i;
        // 2. colr(i+2) from (sM,dM) [meta loaded last iter]
        if (i < 14) {
            int bk = i & 1;                           // (i+2)&1
            colQ[bk] = (t < min(dM, 32)) ? g_col[sM + t] : 0;
            sQ[bk] = sM; dQ[bk] = dM;
        }
        // 1. meta(i+3)
        if (i < 13) {
            sM = g_rowptr[n + 3];
            dM = g_deg[n + 3];
        }
        // 3. gather(i+1), ps(i+1), jk(i+1) from colQ[(i+1)&1]
        if (i < 15) {
            int bk = (i + 1) & 1;
            int dn = dQ[bk];
            int cr = colQ[bk];
#pragma unroll
            for (int j = 0; j < 8; j++) {
                int c = (j < dn) ? __shfl_sync(FULLM, cr, j) : (n + 1);
                hvQ[bk][j] = __ldg(&paIn[(size_t)c * 32 + t]);
            }
            psQ[bk] = __ldcs(&psIn[(size_t)(n + 1) * 32 + t]);
            if (MODE) jkQ[bk] = __ldcs(&g_jk[(size_t)(n + 1) * 32 + t]);
            sC[bk] = sQ[bk]; dC[bk] = dn;
        }
        // 4. consume node i
        {
            int bk = i & 1;
            int d = dC[bk];
            float acc = 0.f;
#pragma unroll
            for (int j = 0; j < 8; j++)
                acc += (j < d) ? __half2float(hvQ[bk][j]) : 0.f;
            if (d > 8) {                               // rare tail (P ~ 2%)
                int s = sC[bk];
                for (int e = 8; e < d; e++) {
                    int c = g_col[s + e];
                    acc += __half2float(__ldg(&paIn[(size_t)c * 32 + t]));
                }
            }
            float o = acc * (1.f / (float)max(d, 1)) + __half2float(psQ[bk]);
            o = selu_f(o);
            size_t idx = (size_t)n * 32 + t;
            if (MODE == 0) {
                __stcs(&g_jk[idx], __float2half_rn(o));
            } else {
                __stcs(&g_jk[idx], __float2half_rn(fmaxf(__half2float(jkQ[bk]), o)));
            }
            if (DO_PROJ) oT[w][i][t] = __float2half_rn(o);
        }
    }

    if (DO_PROJ) {
        __syncwarp();
        const __half* ow = &oT[w][0][0];   // [16][32]
        unsigned a[2][4];
#pragma unroll
        for (int s = 0; s < 2; s++) {
            int kc = tig * 2 + s * 16;
            a[s][0] = *(const unsigned*)(ow + (g4)     * 32 + kc);
            a[s][1] = *(const unsigned*)(ow + (g4 + 8) * 32 + kc);
            a[s][2] = *(const unsigned*)(ow + (g4)     * 32 + kc + 8);
            a[s][3] = *(const unsigned*)(ow + (g4 + 8) * 32 + kc + 8);
        }
#pragma unroll
        for (int j = 0; j < 8; j++) {
            float d0 = 0.f, d1 = 0.f, d2 = 0.f, d3 = 0.f;
            mma16816(d0, d1, d2, d3, a[0][0], a[0][1], a[0][2], a[0][3],
                     bF[((j * 2 + 0) * 2 + 0) * 32 + t],
                     bF[((j * 2 + 0) * 2 + 1) * 32 + t]);
            mma16816(d0, d1, d2, d3, a[1][0], a[1][1], a[1][2], a[1][3],
                     bF[((j * 2 + 1) * 2 + 0) * 32 + t],
                     bF[((j * 2 + 1) * 2 + 1) * 32 + t]);
            int n0 = j * 8 + tig * 2;
            size_t rowLo = (size_t)(nb + g4)     * 32;
            size_t rowHi = (size_t)(nb + g4 + 8) * 32;
            if (j < 4) {
                __half2 lo = __floats2half2_rn(d0, d1);
                __half2 hi = __floats2half2_rn(d2, d3);
                *(__half2*)(paOut + rowLo + n0) = lo;
                *(__half2*)(paOut + rowHi + n0) = hi;
            } else {
                float b0 = blS[n0 - 32], b1 = blS[n0 - 31];
                __half2 lo = __floats2half2_rn(d0 + b0, d1 + b1);
                __half2 hi = __floats2half2_rn(d2 + b0, d3 + b1);
                __stcs((__half2*)(psOut + rowLo + n0 - 32), lo);
                __stcs((__half2*)(psOut + rowHi + n0 - 32), hi);
            }
        }
    }
}

// ---------------- attention (1 warp per graph, 4 graphs per 128-thread block) ----------------
__device__ __forceinline__ int sel6(const int o0, const int o1, const int o2,
                                    const int o3, const int o4, const int o5, int si) {
    int r = o0;
    r = (si == 1) ? o1 : r;
    r = (si == 2) ? o2 : r;
    r = (si == 3) ? o3 : r;
    r = (si == 4) ? o4 : r;
    r = (si == 5) ? o5 : r;
    return r;
}

__global__ void __launch_bounds__(128) k_attn(const float* __restrict__ x,
                                              const int* __restrict__ shuf,
                                              const float* __restrict__ wfc,
                                              const float* __restrict__ bfc,
                                              float* __restrict__ out) {
    __shared__ float sA[1024], sW2[1024], sU[32], sV[32], sB2[32];
    __shared__ float sKeys[4][55 * 33];
    __shared__ float sQa[4][6 * 33];
    __shared__ float sKb[4][56];
    __shared__ float sAt[4][6 * 56];

    int tid = threadIdx.x, t = tid & 31, w = tid >> 5;

    for (int i = tid; i < 1024; i += 128) { sA[i] = g_A[i]; sW2[i] = g_W2[i]; }
    if (tid < 32) { sU[tid] = g_u[tid]; sV[tid] = g_v[tid]; sB2[tid] = g_b2[tid]; }
    __syncthreads();

    float cterm = g_c[0];
    int g = blockIdx.x * 4 + w;
    int nbase = g * NNODES;

    unsigned b0 = __ballot_sync(FULLM, x[(size_t)(nbase + t) * 13 + 10] > 0.5f);
    unsigned b1 = __ballot_sync(FULLM,
                                (t < 23) ? (x[(size_t)(nbase + 32 + t) * 13 + 10] > 0.5f) : false);
    int ord[6];
#pragma unroll
    for (int j = 0; j < 6; j++) {
        if (b0) { int p = __ffs(b0) - 1; b0 &= b0 - 1; ord[j] = p; }
        else    { int p = __ffs(b1) - 1; b1 &= b1 - 1; ord[j] = 32 + p; }
    }
    int qr[6];
#pragma unroll
    for (int j = 0; j < 6; j++) {
        int si = shuf[(size_t)g * 6 + j];
        qr[j] = sel6(ord[0], ord[1], ord[2], ord[3], ord[4], ord[5], si);
    }

    for (int k = 0; k < 55; k++)
        sKeys[w][k * 33 + t] = selu_f(__half2float(__ldg(&g_jk[(size_t)(nbase + k) * 32 + t])));
    __syncwarp();

    {
        float acc = cterm;
#pragma unroll
        for (int d = 0; d < 32; d++) acc += sKeys[w][t * 33 + d] * sV[d];
        sKb[w][t] = acc;
        if (t < 23) {
            float a2 = cterm;
#pragma unroll
            for (int d = 0; d < 32; d++) a2 += sKeys[w][(t + 32) * 33 + d] * sV[d];
            sKb[w][t + 32] = a2;
        }
    }

    float qu[6];
#pragma unroll
    for (int q = 0; q < 6; q++) {
        const float* kr = &sKeys[w][qr[q] * 33];
        float pp = kr[t] * sU[t];
#pragma unroll
        for (int off = 16; off; off >>= 1) pp += __shfl_xor_sync(FULLM, pp, off);
        qu[q] = pp;
        float a = 0.f;
#pragma unroll
        for (int d = 0; d < 32; d++) a += kr[d] * sA[d * 32 + t];
        sQa[w][q * 33 + t] = a;
    }
    __syncwarp();

    const float isq = 0.17677669529663687f;  // 1/sqrt(32)
#pragma unroll
    for (int q = 0; q < 6; q++) {
        const float* qa = &sQa[w][q * 33];
        int k1 = (t < 23) ? (t + 32) : 54;
        float s0 = qu[q] + sKb[w][t];
        float s1 = qu[q] + sKb[w][k1];
#pragma unroll
        for (int d = 0; d < 32; d++) {
            float qv = qa[d];
            s0 += qv * sKeys[w][t * 33 + d];
            s1 += qv * sKeys[w][k1 * 33 + d];
        }
        s0 *= isq; s1 *= isq;
        if (t >= 23) s1 = -1e30f;
        float m = fmaxf(s0, s1);
#pragma unroll
        for (int off = 16; off; off >>= 1) m = fmaxf(m, __shfl_xor_sync(FULLM, m, off));
        float e0 = __expf(s0 - m);
        float e1 = (t < 23) ? __expf(s1 - m) : 0.f;
        float sum = e0 + e1;
#pragma unroll
        for (int off = 16; off; off >>= 1) sum += __shfl_xor_sync(FULLM, sum, off);
        float inv = 1.f / sum;
        sAt[w][q * 56 + t] = e0 * inv;
        if (t < 23) sAt[w][q * 56 + t + 32] = e1 * inv;
    }
    __syncwarp();

#pragma unroll
    for (int q = 0; q < 6; q++) {
        float c2 = 0.f;
        for (int k = 0; k < 55; k++) c2 += sAt[w][q * 56 + k] * sKeys[w][k * 33 + t];
        sQa[w][q * 33 + t] = c2;
    }
    __syncwarp();

#pragma unroll
    for (int q = 0; q < 6; q++) {
        float o = sB2[t];
#pragma unroll
        for (int d = 0; d < 32; d++) o += sQa[w][q * 33 + d] * sW2[d * 32 + t];
        sKeys[w][q * 32 + t] = selu_f(o);
    }
    __syncwarp();

    float pj[6] = {0.f, 0.f, 0.f, 0.f, 0.f, 0.f};
#pragma unroll
    for (int i = 0; i < 6; i++) {
        int e = i * 32 + t;
        float v = sKeys[w][e];
#pragma unroll
        for (int j = 0; j < 6; j++) pj[j] += v * wfc[e * 6 + j];
    }
#pragma unroll
    for (int j = 0; j < 6; j++) {
#pragma unroll
        for (int off = 16; off; off >>= 1) pj[j] += __shfl_xor_sync(FULLM, pj[j], off);
    }
    if (t == 0) {
#pragma unroll
        for (int j = 0; j < 6; j++) out[(size_t)g * 6 + j] = pj[j] + bfc[j];
    }
}

// ---------------- launch ----------------
extern "C" void kernel_launch(void* const* d_in, const int* in_sizes, int n_in,
                              void* d_out, int out_size) {
    const float* x    = (const float*)d_in[0];
    const int*   ei   = (const int*)d_in[1];     // int32 (JAX demotes int64)
    const int*   shuf = (const int*)d_in[2];     // int32
    const float* wl0 = (const float*)d_in[3];
    const float* bl0 = (const float*)d_in[4];
    const float* wr0 = (const float*)d_in[5];
    const float* wl  = (const float*)d_in[6];
    const float* bl  = (const float*)d_in[7];
    const float* wr  = (const float*)d_in[8];
    const float* wq  = (const float*)d_in[9];
    const float* bq  = (const float*)d_in[10];
    const float* wk  = (const float*)d_in[11];
    const float* bk  = (const float*)d_in[12];
    const float* wv  = (const float*)d_in[13];
    const float* bv  = (const float*)d_in[14];
    const float* wo  = (const float*)d_in[15];
    const float* bo  = (const float*)d_in[16];
    const float* wfc = (const float*)d_in[17];
    const float* bfc = (const float*)d_in[18];
    float* out = (float*)d_out;

    __half *paA, *paB, *psA, *psB;
    cudaGetSymbolAddress((void**)&paA, g_paA);
    cudaGetSymbolAddress((void**)&paB, g_paB);
    cudaGetSymbolAddress((void**)&psA, g_psA);
    cudaGetSymbolAddress((void**)&psB, g_psB);

    k_prep<<<1, 256>>>(wq, bq, wk, bk, wv, bv, wo, bo);
    k_zero<<<(NTOT + 255) / 256, 256>>>();
    k_hist<<<(ECNT + 255) / 256, 256>>>(ei);
    k_scan1<<<SCAN_NB, 1024>>>();
    k_scan2<<<1, 256>>>();
    k_scan3<<<(NTOT + 255) / 256, 256>>>();
    k_fill<<<(ECNT + 255) / 256, 256>>>(ei);

    // layer-1 inputs
    k_proj0<<<PROJ_BLOCKS, 256>>>(x, wl0, wr0, bl0, paA, psA);
    // layer 1 (jk = h1) + project layer-2 inputs
    k_aggproj<0, 1><<<AGG_BLOCKS, 256>>>(paA, psA, paB, psB,
                                         wl + 0 * 1024, wr + 0 * 1024, bl + 0 * 32);
    // layers 2..4 (jk = max) + project next
    k_aggproj<1, 1><<<AGG_BLOCKS, 256>>>(paB, psB, paA, psA,
                                         wl + 1 * 1024, wr + 1 * 1024, bl + 1 * 32);
    k_aggproj<1, 1><<<AGG_BLOCKS, 256>>>(paA, psA, paB, psB,
                                         wl + 2 * 1024, wr + 2 * 1024, bl + 2 * 32);
    k_aggproj<1, 1><<<AGG_BLOCKS, 256>>>(paB, psB, paA, psA,
                                         wl + 3 * 1024, wr + 3 * 1024, bl + 3 * 32);
    // layer 5: aggregate + jk only
    k_aggproj<1, 0><<<AGG_BLOCKS, 256>>>(paA, psA, nullptr, nullptr,
                                         nullptr, nullptr, nullptr);

    k_attn<<<NB / 4, 128>>>(x, shuf, wfc, bfc, out);
}

// round 14
// speedup vs baseline: 1.6361x; 1.5922x over previous
#include <cuda_runtime.h>
#include <cuda_fp16.h>

#define NB     16384
#define NNODES 55
#define NTOT   (NB * NNODES)      // 901120
#define ECNT   (4 * NTOT)         // 3604480

#define CSR_BLOCKS 296            // 2 per SM — all resident (spin barrier safe)
#define CSR_CHUNK  3072           // 12 items per thread * 256 threads
#define PROJ_BLOCKS 7040          // 7040 * 8 warps * 16 nodes = 901120
#define AGG_BLOCKS  7040

#define FULLM 0xffffffffu

// ---------------- device scratch ----------------
__device__ __half g_paA[NTOT * 32];
__device__ __half g_paB[NTOT * 32];
__device__ __half g_psA[NTOT * 32];
__device__ __half g_psB[NTOT * 32];
__device__ __half g_jk[NTOT * 32];
__device__ int    g_deg[NTOT];
__device__ int    g_rowptr[NTOT];
__device__ int    g_cursor[NTOT];
__device__ int    g_col[ECNT];
__device__ int    g_bsum[CSR_BLOCKS];
__device__ int    g_bsum2[CSR_BLOCKS];
__device__ float  g_A[1024], g_W2[1024], g_u[32], g_v[32], g_b2[32], g_c[1];

// grid barrier state (g_barCount self-resets; g_barGen monotonic across launches)
__device__ unsigned g_barCount = 0;
__device__ volatile unsigned g_barGen = 0;

__device__ __forceinline__ void gridBarrier() {
    __syncthreads();
    if (threadIdx.x == 0) {
        __threadfence();
        unsigned gen = g_barGen;
        if (atomicAdd(&g_barCount, 1u) == CSR_BLOCKS - 1) {
            g_barCount = 0;
            __threadfence();
            g_barGen = gen + 1;
        } else {
            while (g_barGen == gen) { __nanosleep(32); }
        }
    }
    __syncthreads();
}

__device__ __forceinline__ float selu_f(float x) {
    const float sc = 1.0507009873554805f;
    const float sa = 1.7580993408473766f;  // sc * alpha
    return x > 0.f ? sc * x : sa * expm1f(x);
}

__device__ __forceinline__ void mma16816(float& d0, float& d1, float& d2, float& d3,
                                         unsigned a0, unsigned a1, unsigned a2, unsigned a3,
                                         unsigned b0, unsigned b1) {
    asm volatile("mma.sync.aligned.m16n8k16.row.col.f32.f16.f16.f32 "
                 "{%0,%1,%2,%3}, {%4,%5,%6,%7}, {%8,%9}, {%0,%1,%2,%3};"
                 : "+f"(d0), "+f"(d1), "+f"(d2), "+f"(d3)
                 : "r"(a0), "r"(a1), "r"(a2), "r"(a3), "r"(b0), "r"(b1));
}

// ---------------- fused CSR build: zero -> hist -> scan -> fill (one kernel) ----------------
__global__ void __launch_bounds__(256, 2) k_csr(const int* __restrict__ ei) {
    const int b = blockIdx.x, tid = threadIdx.x;
    const int lane = tid & 31, wid = tid >> 5;
    __shared__ int wsum[8];

    // P0: zero degree counters
    for (int i = b * 256 + tid; i < NTOT; i += CSR_BLOCKS * 256) g_deg[i] = 0;
    gridBarrier();

    // P1: histogram of destinations
    for (int e = b * 256 + tid; e < ECNT; e += CSR_BLOCKS * 256)
        atomicAdd(&g_deg[ei[ECNT + e]], 1);
    gridBarrier();

    // P2a: block-local scan (12 items per thread, kept in registers)
    int base = b * CSR_CHUNK + tid * 12;
    int v[12];
    int tsum = 0;
#pragma unroll
    for (int k = 0; k < 12; k++) {
        int idx = base + k;
        v[k] = (idx < NTOT) ? __ldcg(&g_deg[idx]) : 0;
        tsum += v[k];
    }
    int incl = tsum;
#pragma unroll
    for (int off = 1; off < 32; off <<= 1) {
        int nn = __shfl_up_sync(FULLM, incl, off);
        if (lane >= off) incl += nn;
    }
    if (lane == 31) wsum[wid] = incl;
    __syncthreads();
    if (wid == 0) {
        int wv = (lane < 8) ? wsum[lane] : 0;
        int wi = wv;
#pragma unroll
        for (int off = 1; off < 8; off <<= 1) {
            int nn = __shfl_up_sync(FULLM, wi, off);
            if (lane >= off) wi += nn;
        }
        if (lane < 8) wsum[lane] = wi - wv;
        if (lane == 7) g_bsum[b] = wi;     // block total
    }
    __syncthreads();
    int texcl = wsum[wid] + (incl - tsum);
    gridBarrier();

    // P2b: block 0 / warp 0 scans the 296 block totals
    if (b == 0 && wid == 0) {
        int vals[10];
        int s = 0;
#pragma unroll
        for (int k = 0; k < 10; k++) {
            int i = lane * 10 + k;
            vals[k] = (i < CSR_BLOCKS) ? __ldcg(&g_bsum[i]) : 0;
            s += vals[k];
        }
        int incl2 = s;
#pragma unroll
        for (int off = 1; off < 32; off <<= 1) {
            int nn = __shfl_up_sync(FULLM, incl2, off);
            if (lane >= off) incl2 += nn;
        }
        int run = incl2 - s;
#pragma unroll
        for (int k = 0; k < 10; k++) {
            int i = lane * 10 + k;
            if (i < CSR_BLOCKS) g_bsum2[i] = run;
            run += vals[k];
        }
    }
    gridBarrier();

    // P2c: final rowptr + cursor
    {
        int run = __ldcg(&g_bsum2[b]) + texcl;
#pragma unroll
        for (int k = 0; k < 12; k++) {
            int idx = base + k;
            if (idx < NTOT) { g_rowptr[idx] = run; g_cursor[idx] = run; }
            run += v[k];
        }
    }
    gridBarrier();

    // P3: fill adjacency
    for (int e = b * 256 + tid; e < ECNT; e += CSR_BLOCKS * 256) {
        int s = ei[e];
        int d = ei[ECNT + e];
        int p = atomicAdd(&g_cursor[d], 1);
        g_col[p] = s;
    }
}

// ---------------- attention precompute ----------------
__global__ void __launch_bounds__(256) k_prep(
        const float* __restrict__ wq, const float* __restrict__ bq,
        const float* __restrict__ wk, const float* __restrict__ bk,
        const float* __restrict__ wv, const float* __restrict__ bv,
        const float* __restrict__ wo, const float* __restrict__ bo) {
    int tid = threadIdx.x;
    for (int i = tid; i < 1024; i += 256) {
        int d = i >> 5, e = i & 31;
        float a = 0.f, w2 = 0.f;
        for (int o = 0; o < 32; o++) {
            a  += wq[d * 32 + o] * wk[e * 32 + o];
            w2 += wv[d * 32 + o] * wo[o * 32 + e];
        }
        g_A[d * 32 + e]  = a;
        g_W2[d * 32 + e] = w2;
    }
    if (tid < 32) {
        float u = 0.f, v = 0.f, b2 = 0.f;
        for (int o = 0; o < 32; o++) {
            u  += wq[tid * 32 + o] * bk[o];
            v  += wk[tid * 32 + o] * bq[o];
            b2 += bv[o] * wo[o * 32 + tid];
        }
        g_u[tid] = u; g_v[tid] = v; g_b2[tid] = b2 + bo[tid];
    }
    if (tid == 0) {
        float c = 0.f;
        for (int o = 0; o < 32; o++) c += bq[o] * bk[o];
        g_c[0] = c;
    }
}

// ---------------- layer-0 projection ----------------
__global__ void __launch_bounds__(256) k_proj0(const float* __restrict__ x,
                                               const float* __restrict__ wl0,
                                               const float* __restrict__ wr0,
                                               const float* __restrict__ bl0,
                                               __half* __restrict__ paOut,
                                               __half* __restrict__ psOut) {
    __shared__ float2 wS[13 * 32];
    __shared__ float  blS[32];
    int tid = threadIdx.x, t = tid & 31, w = tid >> 5;
    for (int i = tid; i < 13 * 32; i += 256)
        wS[i] = make_float2(wl0[i], wr0[i]);
    if (tid < 32) blS[tid] = bl0[tid];
    __syncthreads();

    int wg = blockIdx.x * 8 + w;
    for (int it = 0; it < 16; it++) {
        int n = wg * 16 + it;
        float xv = (t < 13) ? x[(size_t)n * 13 + t] : 0.f;
        float apa = 0.f, aps = 0.f;
#pragma unroll
        for (int k = 0; k < 13; k++) {
            float xk = __shfl_sync(FULLM, xv, k);
            float2 w2 = wS[k * 32 + t];
            apa = fmaf(xk, w2.x, apa);
            aps = fmaf(xk, w2.y, aps);
        }
        size_t idx = (size_t)n * 32 + t;
        paOut[idx] = __float2half_rn(apa);
        __stcs(&psOut[idx], __float2half_rn(aps + blS[t]));
    }
}

// ---------------- fused aggregate + selu + jk + mma projection ----------------
// half2 gather: row = 16 lanes x half2; each LDG round fetches 2 neighbor rows
// (lanes 0-15 -> neighbor 2r, lanes 16-31 -> neighbor 2r+1), predicated on degree.
// 3-stage pipeline: iter i issues meta(i+3), colr(i+2), gather(i+1), consumes i.
template <int MODE, int DO_PROJ>
__global__ void __launch_bounds__(256) k_aggproj(const __half* __restrict__ paIn,
                                                 const __half* __restrict__ psIn,
                                                 __half* __restrict__ paOut,
                                                 __half* __restrict__ psOut,
                                                 const float* __restrict__ wl,
                                                 const float* __restrict__ wr,
                                                 const float* __restrict__ bl) {
    __shared__ __half   oT[8][16][32];
    __shared__ unsigned bF[1024];
    __shared__ float    blS[32];
    int tid = threadIdx.x, t = tid & 31, w = tid >> 5;
    int g4 = t >> 2, tig = t & 3;
    int hi16 = t >> 4;              // neighbor subgroup (0/1)
    int ch2 = (t & 15) * 2;         // channel pair base for half2 loads

    if (DO_PROJ) {
        for (int i = tid; i < 1024; i += 256) {
            int lane = i & 31;
            int r = (i >> 5) & 1;
            int s = (i >> 6) & 1;
            int j = i >> 7;
            int n = j * 8 + (lane >> 2);
            const float* Wp = (n < 32) ? (wl + n) : (wr + (n - 32));
            int k0 = s * 16 + (lane & 3) * 2 + (r ? 8 : 0);
            __half2 b = __floats2half2_rn(Wp[k0 * 32], Wp[(k0 + 1) * 32]);
            bF[i] = *(unsigned*)&b;
        }
        if (tid < 32) blS[tid] = bl[tid];
        __syncthreads();
    }

    int wg = blockIdx.x * 8 + w;
    int nb = wg * 16;

    // pipeline state (banks by node parity)
    int     colQ[2];                // raw col indices (lane = slot)
    int     sQ[2], dQ[2];           // meta aligned with colQ
    int     sC[2], dC[2];           // consume-stage meta
    __half2 vvQ[2][4];              // gathered half2 values
    __half  psQ[2], jkQ[2];
    int sM, dM;                     // meta for node (i+2) at iter i
    const __half2 hz = __float2half2_rn(0.f);

    // ---- prologue ----
    {
        int s0 = g_rowptr[nb],     d0 = g_deg[nb];
        int s1 = g_rowptr[nb + 1], d1 = g_deg[nb + 1];
        sM = g_rowptr[nb + 2];  dM = g_deg[nb + 2];
        int colr0 = (t < min(d0, 32)) ? g_col[s0 + t] : 0;
        colQ[1] = (t < min(d1, 32)) ? g_col[s1 + t] : 0;
        sQ[1] = s1; dQ[1] = d1;
#pragma unroll
        for (int r = 0; r < 4; r++) {
            int j = 2 * r + hi16;
            int c = __shfl_sync(FULLM, colr0, j);
            vvQ[0][r] = (j < d0) ? *(const __half2*)(paIn + (size_t)c * 32 + ch2) : hz;
        }
        psQ[0] = __ldcs(&psIn[(size_t)nb * 32 + t]);
        if (MODE) jkQ[0] = __ldcs(&g_jk[(size_t)nb * 32 + t]);
        sC[0] = s0; dC[0] = d0;
    }

#pragma unroll
    for (int i = 0; i < 16; i++) {
        int n = nb + i;
        // colr(i+2)
        if (i < 14) {
            int bk = i & 1;
            colQ[bk] = (t < min(dM, 32)) ? g_col[sM + t] : 0;
            sQ[bk] = sM; dQ[bk] = dM;
        }
        // meta(i+3)
        if (i < 13) {
            sM = g_rowptr[n + 3];
            dM = g_deg[n + 3];
        }
        // gather(i+1)
        if (i < 15) {
            int bk = (i + 1) & 1;
            int dn = dQ[bk];
            int cr = colQ[bk];
#pragma unroll
            for (int r = 0; r < 4; r++) {
                int j = 2 * r + hi16;
                int c = __shfl_sync(FULLM, cr, j);
                vvQ[bk][r] = (j < dn) ? *(const __half2*)(paIn + (size_t)c * 32 + ch2) : hz;
            }
            psQ[bk] = __ldcs(&psIn[(size_t)(n + 1) * 32 + t]);
            if (MODE) jkQ[bk] = __ldcs(&g_jk[(size_t)(n + 1) * 32 + t]);
            sC[bk] = sQ[bk]; dC[bk] = dn;
        }
        // consume node i
        {
            int bk = i & 1;
            int d = dC[bk];
            float s0 = 0.f, s1 = 0.f;
#pragma unroll
            for (int r = 0; r < 4; r++) {
                float2 f = __half22float2(vvQ[bk][r]);
                s0 += f.x; s1 += f.y;
            }
            // combine even/odd neighbor subgroups, then redistribute to channel-per-lane
            s0 += __shfl_xor_sync(FULLM, s0, 16);
            s1 += __shfl_xor_sync(FULLM, s1, 16);
            float v0 = __shfl_sync(FULLM, s0, t >> 1);
            float v1 = __shfl_sync(FULLM, s1, t >> 1);
            float acc = (t & 1) ? v1 : v0;
            if (d > 8) {                               // rare tail
                int s = sC[bk];
                for (int e = 8; e < d; e++) {
                    int c = g_col[s + e];
                    acc += __half2float(__ldg(&paIn[(size_t)c * 32 + t]));
                }
            }
            float o = acc * (1.f / (float)max(d, 1)) + __half2float(psQ[bk]);
            o = selu_f(o);
            size_t idx = (size_t)n * 32 + t;
            if (MODE == 0) {
                __stcs(&g_jk[idx], __float2half_rn(o));
            } else {
                __stcs(&g_jk[idx], __float2half_rn(fmaxf(__half2float(jkQ[bk]), o)));
            }
            if (DO_PROJ) oT[w][i][t] = __float2half_rn(o);
        }
    }

    if (DO_PROJ) {
        __syncwarp();
        const __half* ow = &oT[w][0][0];   // [16][32]
        unsigned a[2][4];
#pragma unroll
        for (int s = 0; s < 2; s++) {
            int kc = tig * 2 + s * 16;
            a[s][0] = *(const unsigned*)(ow + (g4)     * 32 + kc);
            a[s][1] = *(const unsigned*)(ow + (g4 + 8) * 32 + kc);
            a[s][2] = *(const unsigned*)(ow + (g4)     * 32 + kc + 8);
            a[s][3] = *(const unsigned*)(ow + (g4 + 8) * 32 + kc + 8);
        }
#pragma unroll
        for (int j = 0; j < 8; j++) {
            float d0 = 0.f, d1 = 0.f, d2 = 0.f, d3 = 0.f;
            mma16816(d0, d1, d2, d3, a[0][0], a[0][1], a[0][2], a[0][3],
                     bF[((j * 2 + 0) * 2 + 0) * 32 + t],
                     bF[((j * 2 + 0) * 2 + 1) * 32 + t]);
            mma16816(d0, d1, d2, d3, a[1][0], a[1][1], a[1][2], a[1][3],
                     bF[((j * 2 + 1) * 2 + 0) * 32 + t],
                     bF[((j * 2 + 1) * 2 + 1) * 32 + t]);
            int n0 = j * 8 + tig * 2;
            size_t rowLo = (size_t)(nb + g4)     * 32;
            size_t rowHi = (size_t)(nb + g4 + 8) * 32;
            if (j < 4) {
                __half2 lo = __floats2half2_rn(d0, d1);
                __half2 hi = __floats2half2_rn(d2, d3);
                *(__half2*)(paOut + rowLo + n0) = lo;
                *(__half2*)(paOut + rowHi + n0) = hi;
            } else {
                float b0 = blS[n0 - 32], b1 = blS[n0 - 31];
                __half2 lo = __floats2half2_rn(d0 + b0, d1 + b1);
                __half2 hi = __floats2half2_rn(d2 + b0, d3 + b1);
                __stcs((__half2*)(psOut + rowLo + n0 - 32), lo);
                __stcs((__half2*)(psOut + rowHi + n0 - 32), hi);
            }
        }
    }
}

// ---------------- attention ----------------
__device__ __forceinline__ int sel6(const int o0, const int o1, const int o2,
                                    const int o3, const int o4, const int o5, int si) {
    int r = o0;
    r = (si == 1) ? o1 : r;
    r = (si == 2) ? o2 : r;
    r = (si == 3) ? o3 : r;
    r = (si == 4) ? o4 : r;
    r = (si == 5) ? o5 : r;
    return r;
}

__global__ void __launch_bounds__(128) k_attn(const float* __restrict__ x,
                                              const int* __restrict__ shuf,
                                              const float* __restrict__ wfc,
                                              const float* __restrict__ bfc,
                                              float* __restrict__ out) {
    __shared__ float sA[1024], sW2[1024], sU[32], sV[32], sB2[32];
    __shared__ float sKeys[4][55 * 33];
    __shared__ float sQa[4][6 * 33];
    __shared__ float sKb[4][56];
    __shared__ float sAt[4][6 * 56];

    int tid = threadIdx.x, t = tid & 31, w = tid >> 5;

    for (int i = tid; i < 1024; i += 128) { sA[i] = g_A[i]; sW2[i] = g_W2[i]; }
    if (tid < 32) { sU[tid] = g_u[tid]; sV[tid] = g_v[tid]; sB2[tid] = g_b2[tid]; }
    __syncthreads();

    float cterm = g_c[0];
    int g = blockIdx.x * 4 + w;
    int nbase = g * NNODES;

    unsigned b0 = __ballot_sync(FULLM, x[(size_t)(nbase + t) * 13 + 10] > 0.5f);
    unsigned b1 = __ballot_sync(FULLM,
                                (t < 23) ? (x[(size_t)(nbase + 32 + t) * 13 + 10] > 0.5f) : false);
    int ord[6];
#pragma unroll
    for (int j = 0; j < 6; j++) {
        if (b0) { int p = __ffs(b0) - 1; b0 &= b0 - 1; ord[j] = p; }
        else    { int p = __ffs(b1) - 1; b1 &= b1 - 1; ord[j] = 32 + p; }
    }
    int qr[6];
#pragma unroll
    for (int j = 0; j < 6; j++) {
        int si = shuf[(size_t)g * 6 + j];
        qr[j] = sel6(ord[0], ord[1], ord[2], ord[3], ord[4], ord[5], si);
    }

    for (int k = 0; k < 55; k++)
        sKeys[w][k * 33 + t] = selu_f(__half2float(__ldg(&g_jk[(size_t)(nbase + k) * 32 + t])));
    __syncwarp();

    {
        float acc = cterm;
#pragma unroll
        for (int d = 0; d < 32; d++) acc += sKeys[w][t * 33 + d] * sV[d];
        sKb[w][t] = acc;
        if (t < 23) {
            float a2 = cterm;
#pragma unroll
            for (int d = 0; d < 32; d++) a2 += sKeys[w][(t + 32) * 33 + d] * sV[d];
            sKb[w][t + 32] = a2;
        }
    }

    float qu[6];
#pragma unroll
    for (int q = 0; q < 6; q++) {
        const float* kr = &sKeys[w][qr[q] * 33];
        float pp = kr[t] * sU[t];
#pragma unroll
        for (int off = 16; off; off >>= 1) pp += __shfl_xor_sync(FULLM, pp, off);
        qu[q] = pp;
        float a = 0.f;
#pragma unroll
        for (int d = 0; d < 32; d++) a += kr[d] * sA[d * 32 + t];
        sQa[w][q * 33 + t] = a;
    }
    __syncwarp();

    const float isq = 0.17677669529663687f;  // 1/sqrt(32)
#pragma unroll
    for (int q = 0; q < 6; q++) {
        const float* qa = &sQa[w][q * 33];
        int k1 = (t < 23) ? (t + 32) : 54;
        float s0 = qu[q] + sKb[w][t];
        float s1 = qu[q] + sKb[w][k1];
#pragma unroll
        for (int d = 0; d < 32; d++) {
            float qv = qa[d];
            s0 += qv * sKeys[w][t * 33 + d];
            s1 += qv * sKeys[w][k1 * 33 + d];
        }
        s0 *= isq; s1 *= isq;
        if (t >= 23) s1 = -1e30f;
        float m = fmaxf(s0, s1);
#pragma unroll
        for (int off = 16; off; off >>= 1) m = fmaxf(m, __shfl_xor_sync(FULLM, m, off));
        float e0 = __expf(s0 - m);
        float e1 = (t < 23) ? __expf(s1 - m) : 0.f;
        float sum = e0 + e1;
#pragma unroll
        for (int off = 16; off; off >>= 1) sum += __shfl_xor_sync(FULLM, sum, off);
        float inv = 1.f / sum;
        sAt[w][q * 56 + t] = e0 * inv;
        if (t < 23) sAt[w][q * 56 + t + 32] = e1 * inv;
    }
    __syncwarp();

#pragma unroll
    for (int q = 0; q < 6; q++) {
        float c2 = 0.f;
        for (int k = 0; k < 55; k++) c2 += sAt[w][q * 56 + k] * sKeys[w][k * 33 + t];
        sQa[w][q * 33 + t] = c2;
    }
    __syncwarp();

#pragma unroll
    for (int q = 0; q < 6; q++) {
        float o = sB2[t];
#pragma unroll
        for (int d = 0; d < 32; d++) o += sQa[w][q * 33 + d] * sW2[d * 32 + t];
        sKeys[w][q * 32 + t] = selu_f(o);
    }
    __syncwarp();

    float pj[6] = {0.f, 0.f, 0.f, 0.f, 0.f, 0.f};
#pragma unroll
    for (int i = 0; i < 6; i++) {
        int e = i * 32 + t;
        float v = sKeys[w][e];
#pragma unroll
        for (int j = 0; j < 6; j++) pj[j] += v * wfc[e * 6 + j];
    }
#pragma unroll
    for (int j = 0; j < 6; j++) {
#pragma unroll
        for (int off = 16; off; off >>= 1) pj[j] += __shfl_xor_sync(FULLM, pj[j], off);
    }
    if (t == 0) {
#pragma unroll
        for (int j = 0; j < 6; j++) out[(size_t)g * 6 + j] = pj[j] + bfc[j];
    }
}

// ---------------- launch ----------------
extern "C" void kernel_launch(void* const* d_in, const int* in_sizes, int n_in,
                              void* d_out, int out_size) {
    const float* x    = (const float*)d_in[0];
    const int*   ei   = (const int*)d_in[1];     // int32 (JAX demotes int64)
    const int*   shuf = (const int*)d_in[2];     // int32
    const float* wl0 = (const float*)d_in[3];
    const float* bl0 = (const float*)d_in[4];
    const float* wr0 = (const float*)d_in[5];
    const float* wl  = (const float*)d_in[6];
    const float* bl  = (const float*)d_in[7];
    const float* wr  = (const float*)d_in[8];
    const float* wq  = (const float*)d_in[9];
    const float* bq  = (const float*)d_in[10];
    const float* wk  = (const float*)d_in[11];
    const float* bk  = (const float*)d_in[12];
    const float* wv  = (const float*)d_in[13];
    const float* bv  = (const float*)d_in[14];
    const float* wo  = (const float*)d_in[15];
    const float* bo  = (const float*)d_in[16];
    const float* wfc = (const float*)d_in[17];
    const float* bfc = (const float*)d_in[18];
    float* out = (float*)d_out;

    __half *paA, *paB, *psA, *psB;
    cudaGetSymbolAddress((void**)&paA, g_paA);
    cudaGetSymbolAddress((void**)&paB, g_paB);
    cudaGetSymbolAddress((void**)&psA, g_psA);
    cudaGetSymbolAddress((void**)&psB, g_psB);

    k_csr<<<CSR_BLOCKS, 256>>>(ei);                          // 0
    k_proj0<<<PROJ_BLOCKS, 256>>>(x, wl0, wr0, bl0, paA, psA); // 1
    k_prep<<<1, 256>>>(wq, bq, wk, bk, wv, bv, wo, bo);      // 2

    // layer 1 (jk = h1) + project layer-2 inputs      -> launch index 3 (profiled)
    k_aggproj<0, 1><<<AGG_BLOCKS, 256>>>(paA, psA, paB, psB,
                                         wl + 0 * 1024, wr + 0 * 1024, bl + 0 * 32);
    // layers 2..4 (jk = max) + project next
    k_aggproj<1, 1><<<AGG_BLOCKS, 256>>>(paB, psB, paA, psA,
                                         wl + 1 * 1024, wr + 1 * 1024, bl + 1 * 32);
    k_aggproj<1, 1><<<AGG_BLOCKS, 256>>>(paA, psA, paB, psB,
                                         wl + 2 * 1024, wr + 2 * 1024, bl + 2 * 32);
    k_aggproj<1, 1><<<AGG_BLOCKS, 256>>>(paB, psB, paA, psA,
                                         wl + 3 * 1024, wr + 3 * 1024, bl + 3 * 32);
    // layer 5: aggregate + jk only
    k_aggproj<1, 0><<<AGG_BLOCKS, 256>>>(paA, psA, nullptr, nullptr,
                                         nullptr, nullptr, nullptr);

    k_attn<<<NB / 4, 128>>>(x, shuf, wfc, bfc, out);
}

// round 16
// speedup vs baseline: 1.7797x; 1.0878x over previous
#include <cuda_runtime.h>
#include <cuda_fp16.h>

#define NB     16384
#define NNODES 55
#define NTOT   (NB * NNODES)      // 901120
#define ECNT   (4 * NTOT)         // 3604480

#define CSR_BLOCKS 296            // 2 per SM — all resident (spin barrier safe)
#define CSR_CHUNK  3072           // 12 items per thread * 256 threads
#define PROJ_BLOCKS 7040          // 7040 * 8 warps * 16 nodes = 901120
#define AGG_BLOCKS  7040

#define FULLM 0xffffffffu

// ---------------- device scratch ----------------
__device__ __half g_paA[NTOT * 32];
__device__ __half g_paB[NTOT * 32];
__device__ __half g_psA[NTOT * 32];
__device__ __half g_psB[NTOT * 32];
__device__ __half g_jk[NTOT * 32];
__device__ int    g_deg[NTOT];
__device__ int    g_rowptr[NTOT];
__device__ int    g_cursor[NTOT];
__device__ int    g_col[ECNT];
__device__ int    g_total;
__device__ float  g_A[1024], g_W2[1024], g_u[32], g_v[32], g_b2[32], g_c[1];

// grid barrier state (g_barCount self-resets; g_barGen monotonic across launches)
__device__ unsigned g_barCount = 0;
__device__ volatile unsigned g_barGen = 0;

__device__ __forceinline__ void gridBarrier() {
    __syncthreads();
    if (threadIdx.x == 0) {
        __threadfence();
        unsigned gen = g_barGen;
        if (atomicAdd(&g_barCount, 1u) == CSR_BLOCKS - 1) {
            g_barCount = 0;
            __threadfence();
            g_barGen = gen + 1;
        } else {
            while (g_barGen == gen) { __nanosleep(32); }
        }
    }
    __syncthreads();
}

__device__ __forceinline__ float selu_f(float x) {
    const float sc = 1.0507009873554805f;
    const float sa = 1.7580993408473766f;  // sc * alpha
    return x > 0.f ? sc * x : sa * (__expf(x) - 1.f);
}

__device__ __forceinline__ void mma16816(float& d0, float& d1, float& d2, float& d3,
                                         unsigned a0, unsigned a1, unsigned a2, unsigned a3,
                                         unsigned b0, unsigned b1) {
    asm volatile("mma.sync.aligned.m16n8k16.row.col.f32.f16.f16.f32 "
                 "{%0,%1,%2,%3}, {%4,%5,%6,%7}, {%8,%9}, {%0,%1,%2,%3};"
                 : "+f"(d0), "+f"(d1), "+f"(d2), "+f"(d3)
                 : "r"(a0), "r"(a1), "r"(a2), "r"(a3), "r"(b0), "r"(b1));
}

// ---------------- fused CSR build: zero -> hist -> scan(atomic offsets) -> fill ----------------
__global__ void __launch_bounds__(256, 2) k_csr(const int* __restrict__ ei) {
    const int b = blockIdx.x, tid = threadIdx.x;
    const int lane = tid & 31, wid = tid >> 5;
    __shared__ int wsum[8];
    __shared__ int sbase;

    // P0: zero degree counters (+ reset total)
    if (b == 0 && tid == 0) g_total = 0;
    for (int i = b * 256 + tid; i < NTOT; i += CSR_BLOCKS * 256) g_deg[i] = 0;
    gridBarrier();

    // P1: histogram of destinations
    for (int e = b * 256 + tid; e < ECNT; e += CSR_BLOCKS * 256)
        atomicAdd(&g_deg[ei[ECNT + e]], 1);
    gridBarrier();

    // P2: block-local scan (12 items/thread) + atomic block offset
    int base = b * CSR_CHUNK + tid * 12;
    int v[12];
    int tsum = 0;
#pragma unroll
    for (int k = 0; k < 12; k++) {
        int idx = base + k;
        v[k] = (idx < NTOT) ? __ldcg(&g_deg[idx]) : 0;
        tsum += v[k];
    }
    int incl = tsum;
#pragma unroll
    for (int off = 1; off < 32; off <<= 1) {
        int nn = __shfl_up_sync(FULLM, incl, off);
        if (lane >= off) incl += nn;
    }
    if (lane == 31) wsum[wid] = incl;
    __syncthreads();
    if (wid == 0) {
        int wv = (lane < 8) ? wsum[lane] : 0;
        int wi = wv;
#pragma unroll
        for (int off = 1; off < 8; off <<= 1) {
            int nn = __shfl_up_sync(FULLM, wi, off);
            if (lane >= off) wi += nn;
        }
        if (lane < 8) wsum[lane] = wi - wv;
        if (lane == 7) sbase = atomicAdd(&g_total, wi);  // block's segment base
    }
    __syncthreads();
    {
        int run = sbase + wsum[wid] + (incl - tsum);
#pragma unroll
        for (int k = 0; k < 12; k++) {
            int idx = base + k;
            if (idx < NTOT) { g_rowptr[idx] = run; g_cursor[idx] = run; }
            run += v[k];
        }
    }
    gridBarrier();

    // P3: fill adjacency
    for (int e = b * 256 + tid; e < ECNT; e += CSR_BLOCKS * 256) {
        int s = ei[e];
        int d = ei[ECNT + e];
        int p = atomicAdd(&g_cursor[d], 1);
        g_col[p] = s;
    }
}

// ---------------- attention precompute ----------------
__global__ void __launch_bounds__(256) k_prep(
        const float* __restrict__ wq, const float* __restrict__ bq,
        const float* __restrict__ wk, const float* __restrict__ bk,
        const float* __restrict__ wv, const float* __restrict__ bv,
        const float* __restrict__ wo, const float* __restrict__ bo) {
    int tid = threadIdx.x;
    for (int i = tid; i < 1024; i += 256) {
        int d = i >> 5, e = i & 31;
        float a = 0.f, w2 = 0.f;
        for (int o = 0; o < 32; o++) {
            a  += wq[d * 32 + o] * wk[e * 32 + o];
            w2 += wv[d * 32 + o] * wo[o * 32 + e];
        }
        g_A[d * 32 + e]  = a;
        g_W2[d * 32 + e] = w2;
    }
    if (tid < 32) {
        float u = 0.f, v = 0.f, b2 = 0.f;
        for (int o = 0; o < 32; o++) {
            u  += wq[tid * 32 + o] * bk[o];
            v  += wk[tid * 32 + o] * bq[o];
            b2 += bv[o] * wo[o * 32 + tid];
        }
        g_u[tid] = u; g_v[tid] = v; g_b2[tid] = b2 + bo[tid];
    }
    if (tid == 0) {
        float c = 0.f;
        for (int o = 0; o < 32; o++) c += bq[o] * bk[o];
        g_c[0] = c;
    }
}

// ---------------- layer-0 projection ----------------
__global__ void __launch_bounds__(256) k_proj0(const float* __restrict__ x,
                                               const float* __restrict__ wl0,
                                               const float* __restrict__ wr0,
                                               const float* __restrict__ bl0,
                                               __half* __restrict__ paOut,
                                               __half* __restrict__ psOut) {
    __shared__ float2 wS[13 * 32];
    __shared__ float  blS[32];
    int tid = threadIdx.x, t = tid & 31, w = tid >> 5;
    for (int i = tid; i < 13 * 32; i += 256)
        wS[i] = make_float2(wl0[i], wr0[i]);
    if (tid < 32) blS[tid] = bl0[tid];
    __syncthreads();

    int wg = blockIdx.x * 8 + w;
    for (int it = 0; it < 16; it++) {
        int n = wg * 16 + it;
        float xv = (t < 13) ? x[(size_t)n * 13 + t] : 0.f;
        float apa = 0.f, aps = 0.f;
#pragma unroll
        for (int k = 0; k < 13; k++) {
            float xk = __shfl_sync(FULLM, xv, k);
            float2 w2 = wS[k * 32 + t];
            apa = fmaf(xk, w2.x, apa);
            aps = fmaf(xk, w2.y, aps);
        }
        size_t idx = (size_t)n * 32 + t;
        paOut[idx] = __float2half_rn(apa);
        __stcs(&psOut[idx], __float2half_rn(aps + blS[t]));
    }
}

// ---------------- fused aggregate + selu + jk + mma projection ----------------
// half2 gather, 3-stage pipeline (meta i+3 / colr i+2 / gather i+1 / consume i).
// launch_bounds(256,5): cap regs ~51 for 5 blocks/SM.
template <int MODE, int DO_PROJ>
__global__ void __launch_bounds__(256, 5) k_aggproj(const __half* __restrict__ paIn,
                                                    const __half* __restrict__ psIn,
                                                    __half* __restrict__ paOut,
                                                    __half* __restrict__ psOut,
                                                    const float* __restrict__ wl,
                                                    const float* __restrict__ wr,
                                                    const float* __restrict__ bl) {
    __shared__ __half   oT[8][16][32];
    __shared__ unsigned bF[1024];
    __shared__ float    blS[32];
    int tid = threadIdx.x, t = tid & 31, w = tid >> 5;
    int g4 = t >> 2, tig = t & 3;
    int hi16 = t >> 4;              // neighbor subgroup (0/1)
    int ch2 = (t & 15) * 2;         // channel pair base for half2 loads

    if (DO_PROJ) {
        for (int i = tid; i < 1024; i += 256) {
            int lane = i & 31;
            int r = (i >> 5) & 1;
            int s = (i >> 6) & 1;
            int j = i >> 7;
            int n = j * 8 + (lane >> 2);
            const float* Wp = (n < 32) ? (wl + n) : (wr + (n - 32));
            int k0 = s * 16 + (lane & 3) * 2 + (r ? 8 : 0);
            __half2 b = __floats2half2_rn(Wp[k0 * 32], Wp[(k0 + 1) * 32]);
            bF[i] = *(unsigned*)&b;
        }
        if (tid < 32) blS[tid] = bl[tid];
        __syncthreads();
    }

    int wg = blockIdx.x * 8 + w;
    int nb = wg * 16;

    // pipeline state (banks by node parity)
    int     colQ[2];
    int     sQ[2], dQ[2];
    int     dC[2];
    __half2 vvQ[2][4];
    __half  psQ[2], jkQ[2];
    int sM, dM;
    const __half2 hz = __float2half2_rn(0.f);

    // ---- prologue ----
    {
        int s0 = g_rowptr[nb],     d0 = g_deg[nb];
        int s1 = g_rowptr[nb + 1], d1 = g_deg[nb + 1];
        sM = g_rowptr[nb + 2];  dM = g_deg[nb + 2];
        int colr0 = (t < min(d0, 32)) ? g_col[s0 + t] : 0;
        colQ[1] = (t < min(d1, 32)) ? g_col[s1 + t] : 0;
        sQ[1] = s1; dQ[1] = d1;
#pragma unroll
        for (int r = 0; r < 4; r++) {
            int j = 2 * r + hi16;
            int c = __shfl_sync(FULLM, colr0, j);
            vvQ[0][r] = (j < d0) ? *(const __half2*)(paIn + (size_t)c * 32 + ch2) : hz;
        }
        psQ[0] = __ldcs(&psIn[(size_t)nb * 32 + t]);
        if (MODE) jkQ[0] = __ldcs(&g_jk[(size_t)nb * 32 + t]);
        dC[0] = d0;
    }

#pragma unroll
    for (int i = 0; i < 16; i++) {
        int n = nb + i;
        // colr(i+2)
        if (i < 14) {
            int bk = i & 1;
            colQ[bk] = (t < min(dM, 32)) ? g_col[sM + t] : 0;
            sQ[bk] = sM; dQ[bk] = dM;
        }
        // meta(i+3)
        if (i < 13) {
            sM = g_rowptr[n + 3];
            dM = g_deg[n + 3];
        }
        // gather(i+1)
        if (i < 15) {
            int bk = (i + 1) & 1;
            int dn = dQ[bk];
            int cr = colQ[bk];
#pragma unroll
            for (int r = 0; r < 4; r++) {
                int j = 2 * r + hi16;
                int c = __shfl_sync(FULLM, cr, j);
                vvQ[bk][r] = (j < dn) ? *(const __half2*)(paIn + (size_t)c * 32 + ch2) : hz;
            }
            psQ[bk] = __ldcs(&psIn[(size_t)(n + 1) * 32 + t]);
            if (MODE) jkQ[bk] = __ldcs(&g_jk[(size_t)(n + 1) * 32 + t]);
            dC[bk] = dn;
        }
        // consume node i
        {
            int bk = i & 1;
            int d = dC[bk];
            float s0 = 0.f, s1 = 0.f;
#pragma unroll
            for (int r = 0; r < 4; r++) {
                float2 f = __half22float2(vvQ[bk][r]);
                s0 += f.x; s1 += f.y;
            }
            s0 += __shfl_xor_sync(FULLM, s0, 16);
            s1 += __shfl_xor_sync(FULLM, s1, 16);
            float v0 = __shfl_sync(FULLM, s0, t >> 1);
            float v1 = __shfl_sync(FULLM, s1, t >> 1);
            float acc = (t & 1) ? v1 : v0;
            if (d > 8) {                               // rare tail (reload rowptr)
                int s = g_rowptr[n];
                for (int e = 8; e < d; e++) {
                    int c = g_col[s + e];
                    acc += __half2float(__ldg(&paIn[(size_t)c * 32 + t]));
                }
            }
            float o = acc * (1.f / (float)max(d, 1)) + __half2float(psQ[bk]);
            o = selu_f(o);
            size_t idx = (size_t)n * 32 + t;
            if (MODE == 0) {
                __stcs(&g_jk[idx], __float2half_rn(o));
            } else {
                __stcs(&g_jk[idx], __float2half_rn(fmaxf(__half2float(jkQ[bk]), o)));
            }
            if (DO_PROJ) oT[w][i][t] = __float2half_rn(o);
        }
    }

    if (DO_PROJ) {
        __syncwarp();
        const __half* ow = &oT[w][0][0];   // [16][32]
        unsigned a[2][4];
#pragma unroll
        for (int s = 0; s < 2; s++) {
            int kc = tig * 2 + s * 16;
            a[s][0] = *(const unsigned*)(ow + (g4)     * 32 + kc);
            a[s][1] = *(const unsigned*)(ow + (g4 + 8) * 32 + kc);
            a[s][2] = *(const unsigned*)(ow + (g4)     * 32 + kc + 8);
            a[s][3] = *(const unsigned*)(ow + (g4 + 8) * 32 + kc + 8);
        }
#pragma unroll
        for (int j = 0; j < 8; j++) {
            float d0 = 0.f, d1 = 0.f, d2 = 0.f, d3 = 0.f;
            mma16816(d0, d1, d2, d3, a[0][0], a[0][1], a[0][2], a[0][3],
                     bF[((j * 2 + 0) * 2 + 0) * 32 + t],
                     bF[((j * 2 + 0) * 2 + 1) * 32 + t]);
            mma16816(d0, d1, d2, d3, a[1][0], a[1][1], a[1][2], a[1][3],
                     bF[((j * 2 + 1) * 2 + 0) * 32 + t],
                     bF[((j * 2 + 1) * 2 + 1) * 32 + t]);
            int n0 = j * 8 + tig * 2;
            size_t rowLo = (size_t)(nb + g4)     * 32;
            size_t rowHi = (size_t)(nb + g4 + 8) * 32;
            if (j < 4) {
                __half2 lo = __floats2half2_rn(d0, d1);
                __half2 hi = __floats2half2_rn(d2, d3);
                *(__half2*)(paOut + rowLo + n0) = lo;
                *(__half2*)(paOut + rowHi + n0) = hi;
            } else {
                float b0 = blS[n0 - 32], b1 = blS[n0 - 31];
                __half2 lo = __floats2half2_rn(d0 + b0, d1 + b1);
                __half2 hi = __floats2half2_rn(d2 + b0, d3 + b1);
                __stcs((__half2*)(psOut + rowLo + n0 - 32), lo);
                __stcs((__half2*)(psOut + rowHi + n0 - 32), hi);
            }
        }
    }
}

// ---------------- attention ----------------
__device__ __forceinline__ int sel6(const int o0, const int o1, const int o2,
                                    const int o3, const int o4, const int o5, int si) {
    int r = o0;
    r = (si == 1) ? o1 : r;
    r = (si == 2) ? o2 : r;
    r = (si == 3) ? o3 : r;
    r = (si == 4) ? o4 : r;
    r = (si == 5) ? o5 : r;
    return r;
}

__global__ void __launch_bounds__(128) k_attn(const float* __restrict__ x,
                                              const int* __restrict__ shuf,
                                              const float* __restrict__ wfc,
                                              const float* __restrict__ bfc,
                                              float* __restrict__ out) {
    __shared__ float sA[1024], sW2[1024], sU[32], sV[32], sB2[32];
    __shared__ float sKeys[4][55 * 33];
    __shared__ float sQa[4][6 * 33];
    __shared__ float sKb[4][56];
    __shared__ float sAt[4][6 * 56];

    int tid = threadIdx.x, t = tid & 31, w = tid >> 5;

    for (int i = tid; i < 1024; i += 128) { sA[i] = g_A[i]; sW2[i] = g_W2[i]; }
    if (tid < 32) { sU[tid] = g_u[tid]; sV[tid] = g_v[tid]; sB2[tid] = g_b2[tid]; }
    __syncthreads();

    float cterm = g_c[0];
    int g = blockIdx.x * 4 + w;
    int nbase = g * NNODES;

    unsigned b0 = __ballot_sync(FULLM, x[(size_t)(nbase + t) * 13 + 10] > 0.5f);
    unsigned b1 = __ballot_sync(FULLM,
                                (t < 23) ? (x[(size_t)(nbase + 32 + t) * 13 + 10] > 0.5f) : false);
    int ord[6];
#pragma unroll
    for (int j = 0; j < 6; j++) {
        if (b0) { int p = __ffs(b0) - 1; b0 &= b0 - 1; ord[j] = p; }
        else    { int p = __ffs(b1) - 1; b1 &= b1 - 1; ord[j] = 32 + p; }
    }
    int qr[6];
#pragma unroll
    for (int j = 0; j < 6; j++) {
        int si = shuf[(size_t)g * 6 + j];
        qr[j] = sel6(ord[0], ord[1], ord[2], ord[3], ord[4], ord[5], si);
    }

    for (int k = 0; k < 55; k++)
        sKeys[w][k * 33 + t] = selu_f(__half2float(__ldcs(&g_jk[(size_t)(nbase + k) * 32 + t])));
    __syncwarp();

    {
        float acc = cterm;
#pragma unroll
        for (int d = 0; d < 32; d++) acc += sKeys[w][t * 33 + d] * sV[d];
        sKb[w][t] = acc;
        if (t < 23) {
            float a2 = cterm;
#pragma unroll
            for (int d = 0; d < 32; d++) a2 += sKeys[w][(t + 32) * 33 + d] * sV[d];
            sKb[w][t + 32] = a2;
        }
    }

    float qu[6];
#pragma unroll
    for (int q = 0; q < 6; q++) {
        const float* kr = &sKeys[w][qr[q] * 33];
        float pp = kr[t] * sU[t];
#pragma unroll
        for (int off = 16; off; off >>= 1) pp += __shfl_xor_sync(FULLM, pp, off);
        qu[q] = pp;
        float a = 0.f;
#pragma unroll
        for (int d = 0; d < 32; d++) a += kr[d] * sA[d * 32 + t];
        sQa[w][q * 33 + t] = a;
    }
    __syncwarp();

    const float isq = 0.17677669529663687f;  // 1/sqrt(32)
#pragma unroll
    for (int q = 0; q < 6; q++) {
        const float* qa = &sQa[w][q * 33];
        int k1 = (t < 23) ? (t + 32) : 54;
        float s0 = qu[q] + sKb[w][t];
        float s1 = qu[q] + sKb[w][k1];
#pragma unroll
        for (int d = 0; d < 32; d++) {
            float qv = qa[d];
            s0 += qv * sKeys[w][t * 33 + d];
            s1 += qv * sKeys[w][k1 * 33 + d];
        }
        s0 *= isq; s1 *= isq;
        if (t >= 23) s1 = -1e30f;
        float m = fmaxf(s0, s1);
#pragma unroll
        for (int off = 16; off; off >>= 1) m = fmaxf(m, __shfl_xor_sync(FULLM, m, off));
        float e0 = __expf(s0 - m);
        float e1 = (t < 23) ? __expf(s1 - m) : 0.f;
        float sum = e0 + e1;
#pragma unroll
        for (int off = 16; off; off >>= 1) sum += __shfl_xor_sync(FULLM, sum, off);
        float inv = 1.f / sum;
        sAt[w][q * 56 + t] = e0 * inv;
        if (t < 23) sAt[w][q * 56 + t + 32] = e1 * inv;
    }
    __syncwarp();

#pragma unroll
    for (int q = 0; q < 6; q++) {
        float c2 = 0.f;
        for (int k = 0; k < 55; k++) c2 += sAt[w][q * 56 + k] * sKeys[w][k * 33 + t];
        sQa[w][q * 33 + t] = c2;
    }
    __syncwarp();

#pragma unroll
    for (int q = 0; q < 6; q++) {
        float o = sB2[t];
#pragma unroll
        for (int d = 0; d < 32; d++) o += sQa[w][q * 33 + d] * sW2[d * 32 + t];
        sKeys[w][q * 32 + t] = selu_f(o);
    }
    __syncwarp();

    float pj[6] = {0.f, 0.f, 0.f, 0.f, 0.f, 0.f};
#pragma unroll
    for (int i = 0; i < 6; i++) {
        int e = i * 32 + t;
        float v = sKeys[w][e];
#pragma unroll
        for (int j = 0; j < 6; j++) pj[j] += v * wfc[e * 6 + j];
    }
#pragma unroll
    for (int j = 0; j < 6; j++) {
#pragma unroll
        for (int off = 16; off; off >>= 1) pj[j] += __shfl_xor_sync(FULLM, pj[j], off);
    }
    if (t == 0) {
#pragma unroll
        for (int j = 0; j < 6; j++) out[(size_t)g * 6 + j] = pj[j] + bfc[j];
    }
}

// ---------------- launch ----------------
extern "C" void kernel_launch(void* const* d_in, const int* in_sizes, int n_in,
                              void* d_out, int out_size) {
    const float* x    = (const float*)d_in[0];
    const int*   ei   = (const int*)d_in[1];     // int32 (JAX demotes int64)
    const int*   shuf = (const int*)d_in[2];     // int32
    const float* wl0 = (const float*)d_in[3];
    const float* bl0 = (const float*)d_in[4];
    const float* wr0 = (const float*)d_in[5];
    const float* wl  = (const float*)d_in[6];
    const float* bl  = (const float*)d_in[7];
    const float* wr  = (const float*)d_in[8];
    const float* wq  = (const float*)d_in[9];
    const float* bq  = (const float*)d_in[10];
    const float* wk  = (const float*)d_in[11];
    const float* bk  = (const float*)d_in[12];
    const float* wv  = (const float*)d_in[13];
    const float* bv  = (const float*)d_in[14];
    const float* wo  = (const float*)d_in[15];
    const float* bo  = (const float*)d_in[16];
    const float* wfc = (const float*)d_in[17];
    const float* bfc = (const float*)d_in[18];
    float* out = (float*)d_out;

    __half *paA, *paB, *psA, *psB;
    cudaGetSymbolAddress((void**)&paA, g_paA);
    cudaGetSymbolAddress((void**)&paB, g_paB);
    cudaGetSymbolAddress((void**)&psA, g_psA);
    cudaGetSymbolAddress((void**)&psB, g_psB);

    k_csr<<<CSR_BLOCKS, 256>>>(ei);                            // 0
    k_proj0<<<PROJ_BLOCKS, 256>>>(x, wl0, wr0, bl0, paA, psA); // 1
    k_prep<<<1, 256>>>(wq, bq, wk, bk, wv, bv, wo, bo);        // 2

    // layer 1 (jk = h1) + project layer-2 inputs      -> launch index 3 (profiled)
    k_aggproj<0, 1><<<AGG_BLOCKS, 256>>>(paA, psA, paB, psB,
                                         wl + 0 * 1024, wr + 0 * 1024, bl + 0 * 32);
    // layers 2..4 (jk = max) + project next
    k_aggproj<1, 1><<<AGG_BLOCKS, 256>>>(paB, psB, paA, psA,
                                         wl + 1 * 1024, wr + 1 * 1024, bl + 1 * 32);
    k_aggproj<1, 1><<<AGG_BLOCKS, 256>>>(paA, psA, paB, psB,
                                         wl + 2 * 1024, wr + 2 * 1024, bl + 2 * 32);
    k_aggproj<1, 1><<<AGG_BLOCKS, 256>>>(paB, psB, paA, psA,
                                         wl + 3 * 1024, wr + 3 * 1024, bl + 3 * 32);
    // layer 5: aggregate + jk only
    k_aggproj<1, 0><<<AGG_BLOCKS, 256>>>(paA, psA, nullptr, nullptr,
                                         nullptr, nullptr, nullptr);

    k_attn<<<NB / 4, 128>>>(x, shuf, wfc, bfc, out);
}